// round 4
// baseline (speedup 1.0000x reference)
#include <cuda_runtime.h>
#include <cuda_bf16.h>
#include <cstdint>

#define D 128
#define D4 32            // D/4 float4 per row
#define MAXN 100000
#define MAXE 1600000
#define GEMM_ROWS 64
#define GEMM_TY 8
#define ROWS_PER_T (GEMM_ROWS / GEMM_TY)   // 8
#define SCAN_T 1024

// ---- scratch (device globals; 16B-aligned via float4) ----
__device__ float4 g_mean[MAXN * D4];     // per-node mean of neighbor features
__device__ float4 g_h[MAXN * D4];        // layer-1 output
__device__ int    g_cnt[MAXN];
__device__ int    g_off[MAXN + 1];
__device__ int    g_cur[MAXN];
__device__ int    g_eidx[MAXE];          // src indices grouped by dst (CSR)
__device__ int    g_is64;                // edge_index dtype flag

// ---------------- dtype detection ----------------
// int64 edge data: every 8-byte word < 2^32 (indices < 100000, nonneg).
// int32 edge data read as 8-byte words: lo | (hi<<32), hi != 0 almost surely.
__global__ void detect_kernel(const unsigned long long* __restrict__ ei, int E) {
    if (threadIdx.x == 0 && blockIdx.x == 0) {
        int is64 = 1;
        int n = E < 1024 ? E : 1024;
        for (int i = 0; i < n; i++) {
            if (ei[i] > 0xFFFFFFFFULL) { is64 = 0; break; }
        }
        g_is64 = is64;
    }
}

__device__ __forceinline__ void load_edge(const void* ei, int E, int e, int is64,
                                          int N, int& s, int& d) {
    if (is64) {
        const long long* p = (const long long*)ei;
        s = (int)p[e];
        d = (int)p[(size_t)E + e];
    } else {
        const int* p = (const int*)ei;
        s = p[e];
        d = p[E + e];
    }
    // safety clamp (no-op for valid data)
    s = (s < 0) ? 0 : (s >= N ? N - 1 : s);
    d = (d < 0) ? 0 : (d >= N ? N - 1 : d);
}

// ---------------- CSR build ----------------
__global__ void zero_cnt_kernel(int n) {
    int i = blockIdx.x * blockDim.x + threadIdx.x;
    if (i < n) g_cnt[i] = 0;
}

__global__ void count_kernel(const void* __restrict__ ei, int E, int N) {
    int e = blockIdx.x * blockDim.x + threadIdx.x;
    if (e < E) {
        int is64 = g_is64;
        int s, d;
        load_edge(ei, E, e, is64, N, s, d);
        atomicAdd(&g_cnt[d], 1);
    }
}

// single-block exclusive scan over g_cnt -> g_off / g_cur
__global__ void scan_kernel(int n) {
    __shared__ int ssum[SCAN_T];
    int t = threadIdx.x;
    int chunk = (n + SCAN_T - 1) / SCAN_T;
    int b = t * chunk;
    int e = b + chunk; if (e > n) e = n;
    int s = 0;
    for (int i = b; i < e; i++) s += g_cnt[i];
    ssum[t] = s;
    __syncthreads();
    for (int off = 1; off < SCAN_T; off <<= 1) {
        int v = (t >= off) ? ssum[t - off] : 0;
        __syncthreads();
        ssum[t] += v;
        __syncthreads();
    }
    int run = (t == 0) ? 0 : ssum[t - 1];
    for (int i = b; i < e; i++) {
        g_off[i] = run;
        g_cur[i] = run;
        run += g_cnt[i];
    }
    if (e == n && b < n) g_off[n] = run;
    if (t == SCAN_T - 1) g_off[n] = ssum[SCAN_T - 1];
}

__global__ void fill_kernel(const void* __restrict__ ei, int E, int N) {
    int e = blockIdx.x * blockDim.x + threadIdx.x;
    if (e < E) {
        int is64 = g_is64;
        int s, d;
        load_edge(ei, E, e, is64, N, s, d);
        int p = atomicAdd(&g_cur[d], 1);
        if (p >= 0 && p < MAXE) g_eidx[p] = s;
    }
}

// ---------------- aggregation: warp per node, register accumulation ----------------
__global__ void aggregate_kernel(const float* __restrict__ xext, int use_gh, int N) {
    int warp = (blockIdx.x * blockDim.x + threadIdx.x) >> 5;
    int lane = threadIdx.x & 31;
    if (warp >= N) return;
    const float4* feat = use_gh ? g_h : (const float4*)xext;

    int beg = g_off[warp];
    int end = g_off[warp + 1];
    int cnt = end - beg;

    float4 acc = make_float4(0.f, 0.f, 0.f, 0.f);
    int e = beg;
    for (; e + 4 <= end; e += 4) {
        int s0 = g_eidx[e + 0];
        int s1 = g_eidx[e + 1];
        int s2 = g_eidx[e + 2];
        int s3 = g_eidx[e + 3];
        float4 v0 = feat[(size_t)s0 * D4 + lane];
        float4 v1 = feat[(size_t)s1 * D4 + lane];
        float4 v2 = feat[(size_t)s2 * D4 + lane];
        float4 v3 = feat[(size_t)s3 * D4 + lane];
        acc.x += (v0.x + v1.x) + (v2.x + v3.x);
        acc.y += (v0.y + v1.y) + (v2.y + v3.y);
        acc.z += (v0.z + v1.z) + (v2.z + v3.z);
        acc.w += (v0.w + v1.w) + (v2.w + v3.w);
    }
    for (; e < end; e++) {
        int s = g_eidx[e];
        float4 v = feat[(size_t)s * D4 + lane];
        acc.x += v.x; acc.y += v.y; acc.z += v.z; acc.w += v.w;
    }
    float inv = 1.0f / fmaxf((float)cnt, 1.0f);
    acc.x *= inv; acc.y *= inv; acc.z *= inv; acc.w *= inv;
    g_mean[(size_t)warp * D4 + lane] = acc;
}

// ---------------- fused SAGE GEMM ----------------
// out[i][:] = g_mean[i] @ Wl + in[i] @ Wr + b
__global__ void gemm_fused_kernel(const float* __restrict__ xext, int use_gh_in,
                                  const float* __restrict__ Wl,
                                  const float* __restrict__ Wr,
                                  const float* __restrict__ bias,
                                  float* __restrict__ oext, int use_gh_out,
                                  int nrows) {
    extern __shared__ float sm[];
    float* sWl = sm;                  // 16384
    float* sWr = sm + 16384;          // 16384
    float* sM  = sm + 32768;          // 64*128
    float* sX  = sm + 32768 + GEMM_ROWS * D;

    const float4* xin = use_gh_in ? g_h : (const float4*)xext;
    float4* out = use_gh_out ? g_h : (float4*)oext;

    int tid = threadIdx.y * 32 + threadIdx.x;
    int row0 = blockIdx.x * GEMM_ROWS;

    for (int i = tid; i < 4096; i += 256) {
        ((float4*)sWl)[i] = ((const float4*)Wl)[i];
        ((float4*)sWr)[i] = ((const float4*)Wr)[i];
    }
    for (int i = tid; i < GEMM_ROWS * D4; i += 256) {
        int r = i >> 5;
        int c = i & 31;
        int gr = row0 + r;
        int grc = gr < nrows ? gr : (nrows - 1);
        ((float4*)sM)[i] = g_mean[(size_t)grc * D4 + c];
        ((float4*)sX)[i] = xin[(size_t)grc * D4 + c];
    }
    __syncthreads();

    int j0 = threadIdx.x * 4;
    int r0 = threadIdx.y * ROWS_PER_T;

    float4 acc[ROWS_PER_T];
    #pragma unroll
    for (int r = 0; r < ROWS_PER_T; r++) acc[r] = make_float4(0.f, 0.f, 0.f, 0.f);

    #pragma unroll 4
    for (int k = 0; k < D; k++) {
        float4 wl = *(const float4*)&sWl[k * D + j0];
        float4 wr = *(const float4*)&sWr[k * D + j0];
        #pragma unroll
        for (int r = 0; r < ROWS_PER_T; r++) {
            float mv = sM[(r0 + r) * D + k];
            float xv = sX[(r0 + r) * D + k];
            acc[r].x += mv * wl.x + xv * wr.x;
            acc[r].y += mv * wl.y + xv * wr.y;
            acc[r].z += mv * wl.z + xv * wr.z;
            acc[r].w += mv * wl.w + xv * wr.w;
        }
    }

    float4 bv = ((const float4*)bias)[threadIdx.x];
    #pragma unroll
    for (int r = 0; r < ROWS_PER_T; r++) {
        int gr = row0 + r0 + r;
        if (gr < nrows) {
            float4 o;
            o.x = acc[r].x + bv.x;
            o.y = acc[r].y + bv.y;
            o.z = acc[r].z + bv.z;
            o.w = acc[r].w + bv.w;
            out[(size_t)gr * D4 + threadIdx.x] = o;
        }
    }
}

// ---------------- launch ----------------
extern "C" void kernel_launch(void* const* d_in, const int* in_sizes, int n_in,
                              void* d_out, int out_size) {
    const float* x  = (const float*)d_in[0];
    const void*  ei = d_in[1];
    int off = n_in - 6;
    const float* Wl1 = (const float*)d_in[off + 0];
    const float* bl1 = (const float*)d_in[off + 1];
    const float* Wr1 = (const float*)d_in[off + 2];
    const float* Wl2 = (const float*)d_in[off + 3];
    const float* bl2 = (const float*)d_in[off + 4];
    const float* Wr2 = (const float*)d_in[off + 5];

    int N = in_sizes[0] / D;
    int E = in_sizes[1] / 2;
    int ORIGN = out_size / D;
    float* out = (float*)d_out;

    const int smemBytes = (2 * 16384 + 2 * GEMM_ROWS * D) * 4;   // 192 KB
    cudaFuncSetAttribute(gemm_fused_kernel,
                         cudaFuncAttributeMaxDynamicSharedMemorySize, smemBytes);

    // ---- dtype detect + CSR build (dst-grouped) ----
    // NOTE: if edge data is int32, its byte size is E*2*4; reading the first
    // min(E,1024) 8-byte words stays within the buffer (E >= 2048 here).
    detect_kernel<<<1, 32>>>((const unsigned long long*)ei, E);
    zero_cnt_kernel<<<(N + 255) / 256, 256>>>(N);
    count_kernel<<<(E + 255) / 256, 256>>>(ei, E, N);
    scan_kernel<<<1, SCAN_T>>>(N);
    fill_kernel<<<(E + 255) / 256, 256>>>(ei, E, N);

    int aggGrid = (N * 32 + 255) / 256;
    int gemmGrid1 = (N + GEMM_ROWS - 1) / GEMM_ROWS;
    int gemmGrid2 = (ORIGN + GEMM_ROWS - 1) / GEMM_ROWS;

    // ---- layer 1: mean(x) -> g_mean ; g_h = mean@Wl1 + x@Wr1 + b1 ----
    aggregate_kernel<<<aggGrid, 256>>>(x, 0, N);
    gemm_fused_kernel<<<gemmGrid1, dim3(32, GEMM_TY), smemBytes>>>(
        x, 0, Wl1, Wr1, bl1, nullptr, 1, N);

    // ---- layer 2: mean(g_h) -> g_mean ; out = mean@Wl2 + g_h@Wr2 + b2 ----
    aggregate_kernel<<<aggGrid, 256>>>(nullptr, 1, N);
    gemm_fused_kernel<<<gemmGrid2, dim3(32, GEMM_TY), smemBytes>>>(
        nullptr, 1, Wl2, Wr2, bl2, out, 0, ORIGN);
}

// round 5
// speedup vs baseline: 1.2383x; 1.2383x over previous
#include <cuda_runtime.h>
#include <cuda_bf16.h>
#include <cstdint>

#define D 128
#define D4 32            // D/4 float4 per row
#define MAXN 100000
#define MAXE 1600000
#define GEMM_ROWS 64
#define GEMM_TY 8
#define ROWS_PER_T (GEMM_ROWS / GEMM_TY)   // 8
#define SCAN_TILE 1024
#define MAXB ((MAXN + SCAN_TILE - 1) / SCAN_TILE)   // 98

// ---- scratch (device globals; 16B-aligned via float4) ----
__device__ float4 g_mean[MAXN * D4];     // per-node mean of neighbor features
__device__ float4 g_h[MAXN * D4];        // layer-1 output
__device__ int    g_cnt[MAXN];
__device__ int    g_off[MAXN + 1];
__device__ int    g_cur[MAXN];
__device__ int    g_bsum[MAXB + 1];
__device__ int    g_eidx[MAXE];          // src indices grouped by dst (CSR)
__device__ int    g_is64;                // edge_index dtype flag

// ---------------- dtype detection (parallel) ----------------
// int64 edge data: every 8-byte word < 2^32 (indices < 100000, nonneg).
// int32 data read as 8-byte words: lo | (hi<<32) with hi!=0 almost surely.
__global__ void detect_kernel(const unsigned long long* __restrict__ ei, int E) {
    __shared__ int any_big;
    if (threadIdx.x == 0) any_big = 0;
    __syncthreads();
    int n = E < 1024 ? E : 1024;
    int i = threadIdx.x;
    int big = (i < n && ei[i] > 0xFFFFFFFFULL) ? 1 : 0;
    if (__syncthreads_or(big)) {
        if (threadIdx.x == 0) g_is64 = 0;
    } else {
        if (threadIdx.x == 0) g_is64 = 1;
    }
}

__device__ __forceinline__ void load_edge(const void* ei, int E, int e, int is64,
                                          int N, int& s, int& d) {
    if (is64) {
        const long long* p = (const long long*)ei;
        s = (int)p[e];
        d = (int)p[(size_t)E + e];
    } else {
        const int* p = (const int*)ei;
        s = p[e];
        d = p[E + e];
    }
    s = (s < 0) ? 0 : (s >= N ? N - 1 : s);
    d = (d < 0) ? 0 : (d >= N ? N - 1 : d);
}

// ---------------- CSR build ----------------
__global__ void zero_cnt_kernel(int n) {
    int i = blockIdx.x * blockDim.x + threadIdx.x;
    if (i < n) g_cnt[i] = 0;
}

__global__ void count_kernel(const void* __restrict__ ei, int E, int N) {
    int e = blockIdx.x * blockDim.x + threadIdx.x;
    if (e < E) {
        int s, d;
        load_edge(ei, E, e, g_is64, N, s, d);
        atomicAdd(&g_cnt[d], 1);
    }
}

// ---- 3-phase parallel exclusive scan over g_cnt[0..n) -> g_off, g_cur ----
// phase 1: per-block (1024 elems, 256 threads x 4) local exclusive scan + block sum
__global__ void scan1_kernel(int n) {
    __shared__ int wsum[8];
    int t = threadIdx.x;
    int lane = t & 31, wid = t >> 5;
    int i0 = blockIdx.x * SCAN_TILE + t * 4;

    int a0 = 0, a1 = 0, a2 = 0, a3 = 0;
    if (i0 + 3 < n) {
        int4 v = *(const int4*)&g_cnt[i0];
        a0 = v.x; a1 = v.y; a2 = v.z; a3 = v.w;
    } else {
        if (i0     < n) a0 = g_cnt[i0];
        if (i0 + 1 < n) a1 = g_cnt[i0 + 1];
        if (i0 + 2 < n) a2 = g_cnt[i0 + 2];
        if (i0 + 3 < n) a3 = g_cnt[i0 + 3];
    }
    int s = a0 + a1 + a2 + a3;

    // inclusive warp scan of s
    int x = s;
    #pragma unroll
    for (int o = 1; o < 32; o <<= 1) {
        int y = __shfl_up_sync(0xFFFFFFFFu, x, o);
        if (lane >= o) x += y;
    }
    if (lane == 31) wsum[wid] = x;
    __syncthreads();
    if (t < 8) {
        int w = wsum[t];
        #pragma unroll
        for (int o = 1; o < 8; o <<= 1) {
            int y = __shfl_up_sync(0xFFu, w, o);
            if (t >= o) w += y;
        }
        wsum[t] = w;
    }
    __syncthreads();
    int excl = x - s + (wid > 0 ? wsum[wid - 1] : 0);

    if (i0     < n) g_off[i0]     = excl;
    if (i0 + 1 < n) g_off[i0 + 1] = excl + a0;
    if (i0 + 2 < n) g_off[i0 + 2] = excl + a0 + a1;
    if (i0 + 3 < n) g_off[i0 + 3] = excl + a0 + a1 + a2;
    if (t == 0) g_bsum[blockIdx.x] = wsum[7];
}

// phase 2: single block exclusive-scans the block sums (B <= 128)
__global__ void scan2_kernel(int B, int n) {
    __shared__ int sh[128];
    int t = threadIdx.x;
    int v = (t < B) ? g_bsum[t] : 0;
    sh[t] = v;
    __syncthreads();
    for (int o = 1; o < 128; o <<= 1) {
        int y = (t >= o) ? sh[t - o] : 0;
        __syncthreads();
        sh[t] += y;
        __syncthreads();
    }
    if (t < B) g_bsum[t] = sh[t] - v;       // exclusive prefix
    if (t == 127) g_off[n] = sh[127];       // total
}

// phase 3: add block prefix, populate g_cur
__global__ void scan3_kernel(int n) {
    int i0 = blockIdx.x * SCAN_TILE + threadIdx.x * 4;
    int bp = g_bsum[blockIdx.x];
    #pragma unroll
    for (int j = 0; j < 4; j++) {
        int i = i0 + j;
        if (i < n) {
            int v = g_off[i] + bp;
            g_off[i] = v;
            g_cur[i] = v;
        }
    }
}

__global__ void fill_kernel(const void* __restrict__ ei, int E, int N) {
    int e = blockIdx.x * blockDim.x + threadIdx.x;
    if (e < E) {
        int s, d;
        load_edge(ei, E, e, g_is64, N, s, d);
        int p = atomicAdd(&g_cur[d], 1);
        if (p >= 0 && p < MAXE) g_eidx[p] = s;
    }
}

// ---------------- aggregation: warp per node, register accumulation ----------------
__global__ void aggregate_kernel(const float* __restrict__ xext, int use_gh, int N) {
    int warp = (blockIdx.x * blockDim.x + threadIdx.x) >> 5;
    int lane = threadIdx.x & 31;
    if (warp >= N) return;
    const float4* feat = use_gh ? g_h : (const float4*)xext;

    int beg = g_off[warp];
    int end = g_off[warp + 1];
    int cnt = end - beg;

    float4 acc = make_float4(0.f, 0.f, 0.f, 0.f);
    int e = beg;
    for (; e + 4 <= end; e += 4) {
        int s0 = g_eidx[e + 0];
        int s1 = g_eidx[e + 1];
        int s2 = g_eidx[e + 2];
        int s3 = g_eidx[e + 3];
        float4 v0 = feat[(size_t)s0 * D4 + lane];
        float4 v1 = feat[(size_t)s1 * D4 + lane];
        float4 v2 = feat[(size_t)s2 * D4 + lane];
        float4 v3 = feat[(size_t)s3 * D4 + lane];
        acc.x += (v0.x + v1.x) + (v2.x + v3.x);
        acc.y += (v0.y + v1.y) + (v2.y + v3.y);
        acc.z += (v0.z + v1.z) + (v2.z + v3.z);
        acc.w += (v0.w + v1.w) + (v2.w + v3.w);
    }
    for (; e < end; e++) {
        int s = g_eidx[e];
        float4 v = feat[(size_t)s * D4 + lane];
        acc.x += v.x; acc.y += v.y; acc.z += v.z; acc.w += v.w;
    }
    float inv = 1.0f / fmaxf((float)cnt, 1.0f);
    acc.x *= inv; acc.y *= inv; acc.z *= inv; acc.w *= inv;
    g_mean[(size_t)warp * D4 + lane] = acc;
}

// ---------------- fused SAGE GEMM ----------------
// out[i][:] = g_mean[i] @ Wl + in[i] @ Wr + b
__global__ void gemm_fused_kernel(const float* __restrict__ xext, int use_gh_in,
                                  const float* __restrict__ Wl,
                                  const float* __restrict__ Wr,
                                  const float* __restrict__ bias,
                                  float* __restrict__ oext, int use_gh_out,
                                  int nrows) {
    extern __shared__ float sm[];
    float* sWl = sm;                  // 16384
    float* sWr = sm + 16384;          // 16384
    float* sM  = sm + 32768;          // 64*128
    float* sX  = sm + 32768 + GEMM_ROWS * D;

    const float4* xin = use_gh_in ? g_h : (const float4*)xext;
    float4* out = use_gh_out ? g_h : (float4*)oext;

    int tid = threadIdx.y * 32 + threadIdx.x;
    int row0 = blockIdx.x * GEMM_ROWS;

    for (int i = tid; i < 4096; i += 256) {
        ((float4*)sWl)[i] = ((const float4*)Wl)[i];
        ((float4*)sWr)[i] = ((const float4*)Wr)[i];
    }
    for (int i = tid; i < GEMM_ROWS * D4; i += 256) {
        int r = i >> 5;
        int c = i & 31;
        int gr = row0 + r;
        int grc = gr < nrows ? gr : (nrows - 1);
        ((float4*)sM)[i] = g_mean[(size_t)grc * D4 + c];
        ((float4*)sX)[i] = xin[(size_t)grc * D4 + c];
    }
    __syncthreads();

    int j0 = threadIdx.x * 4;
    int r0 = threadIdx.y * ROWS_PER_T;

    float4 acc[ROWS_PER_T];
    #pragma unroll
    for (int r = 0; r < ROWS_PER_T; r++) acc[r] = make_float4(0.f, 0.f, 0.f, 0.f);

    #pragma unroll 4
    for (int k = 0; k < D; k++) {
        float4 wl = *(const float4*)&sWl[k * D + j0];
        float4 wr = *(const float4*)&sWr[k * D + j0];
        #pragma unroll
        for (int r = 0; r < ROWS_PER_T; r++) {
            float mv = sM[(r0 + r) * D + k];
            float xv = sX[(r0 + r) * D + k];
            acc[r].x += mv * wl.x + xv * wr.x;
            acc[r].y += mv * wl.y + xv * wr.y;
            acc[r].z += mv * wl.z + xv * wr.z;
            acc[r].w += mv * wl.w + xv * wr.w;
        }
    }

    float4 bv = ((const float4*)bias)[threadIdx.x];
    #pragma unroll
    for (int r = 0; r < ROWS_PER_T; r++) {
        int gr = row0 + r0 + r;
        if (gr < nrows) {
            float4 o;
            o.x = acc[r].x + bv.x;
            o.y = acc[r].y + bv.y;
            o.z = acc[r].z + bv.z;
            o.w = acc[r].w + bv.w;
            out[(size_t)gr * D4 + threadIdx.x] = o;
        }
    }
}

// ---------------- launch ----------------
extern "C" void kernel_launch(void* const* d_in, const int* in_sizes, int n_in,
                              void* d_out, int out_size) {
    const float* x  = (const float*)d_in[0];
    const void*  ei = d_in[1];
    int off = n_in - 6;
    const float* Wl1 = (const float*)d_in[off + 0];
    const float* bl1 = (const float*)d_in[off + 1];
    const float* Wr1 = (const float*)d_in[off + 2];
    const float* Wl2 = (const float*)d_in[off + 3];
    const float* bl2 = (const float*)d_in[off + 4];
    const float* Wr2 = (const float*)d_in[off + 5];

    int N = in_sizes[0] / D;
    int E = in_sizes[1] / 2;
    int ORIGN = out_size / D;
    float* out = (float*)d_out;

    const int smemBytes = (2 * 16384 + 2 * GEMM_ROWS * D) * 4;   // 192 KB
    cudaFuncSetAttribute(gemm_fused_kernel,
                         cudaFuncAttributeMaxDynamicSharedMemorySize, smemBytes);

    // ---- dtype detect + CSR build (dst-grouped) ----
    detect_kernel<<<1, 1024>>>((const unsigned long long*)ei, E);
    zero_cnt_kernel<<<(N + 255) / 256, 256>>>(N);
    count_kernel<<<(E + 255) / 256, 256>>>(ei, E, N);
    int B = (N + SCAN_TILE - 1) / SCAN_TILE;           // 98
    scan1_kernel<<<B, 256>>>(N);
    scan2_kernel<<<1, 128>>>(B, N);
    scan3_kernel<<<B, 256>>>(N);
    fill_kernel<<<(E + 255) / 256, 256>>>(ei, E, N);

    int aggGrid = (N * 32 + 255) / 256;
    int gemmGrid1 = (N + GEMM_ROWS - 1) / GEMM_ROWS;
    int gemmGrid2 = (ORIGN + GEMM_ROWS - 1) / GEMM_ROWS;

    // ---- layer 1: mean(x) -> g_mean ; g_h = mean@Wl1 + x@Wr1 + b1 ----
    aggregate_kernel<<<aggGrid, 256>>>(x, 0, N);
    gemm_fused_kernel<<<gemmGrid1, dim3(32, GEMM_TY), smemBytes>>>(
        x, 0, Wl1, Wr1, bl1, nullptr, 1, N);

    // ---- layer 2: mean(g_h) -> g_mean ; out = mean@Wl2 + g_h@Wr2 + b2 ----
    aggregate_kernel<<<aggGrid, 256>>>(nullptr, 1, N);
    gemm_fused_kernel<<<gemmGrid2, dim3(32, GEMM_TY), smemBytes>>>(
        nullptr, 1, Wl2, Wr2, bl2, out, 0, ORIGN);
}

// round 6
// speedup vs baseline: 1.7416x; 1.4065x over previous
#include <cuda_runtime.h>
#include <cuda_bf16.h>
#include <cstdint>

#define D 128
#define D4 32            // D/4 float4 per row
#define MAXN 100000
#define MAXE 1600000
#define SCAN_TILE 1024
#define MAXB ((MAXN + SCAN_TILE - 1) / SCAN_TILE)   // 98

// GEMM (mma) tiling
#define BLK_M 64
#define K2 128              // K=256 concat, in bf16x2 pairs
#define SW_STRIDE 132       // padded word stride for W tiles (128 cols)
#define SA_STRIDE 68        // padded word stride for A tiles (64 rows)
#define SW_WORDS (K2 * SW_STRIDE)   // 16896
#define SA_WORDS (K2 * SA_STRIDE)   // 8704
#define GEMM_SMEM_BYTES ((2 * SW_WORDS + 2 * SA_WORDS) * 4)   // 204800

// ---- scratch (device globals; 16B-aligned via float4) ----
__device__ float4 g_mean[MAXN * D4];     // per-node mean of neighbor features
__device__ float4 g_h[MAXN * D4];        // layer-1 output
__device__ int    g_cnt[MAXN];
__device__ int    g_off[MAXN + 1];
__device__ int    g_cur[MAXN];
__device__ int    g_bsum[MAXB + 1];
__device__ int    g_eidx[MAXE];          // src indices grouped by dst (CSR)
__device__ int    g_is64;                // edge_index dtype flag

// ---------------- dtype detection (parallel) ----------------
__global__ void detect_kernel(const unsigned long long* __restrict__ ei, int E) {
    int n = E < 1024 ? E : 1024;
    int i = threadIdx.x;
    int big = (i < n && ei[i] > 0xFFFFFFFFULL) ? 1 : 0;
    int any = __syncthreads_or(big);
    if (threadIdx.x == 0) g_is64 = any ? 0 : 1;
}

__device__ __forceinline__ void load_edge(const void* ei, int E, int e, int is64,
                                          int N, int& s, int& d) {
    if (is64) {
        const long long* p = (const long long*)ei;
        s = (int)p[e];
        d = (int)p[(size_t)E + e];
    } else {
        const int* p = (const int*)ei;
        s = p[e];
        d = p[E + e];
    }
    s = (s < 0) ? 0 : (s >= N ? N - 1 : s);
    d = (d < 0) ? 0 : (d >= N ? N - 1 : d);
}

// ---------------- CSR build ----------------
__global__ void zero_cnt_kernel(int n) {
    int i = blockIdx.x * blockDim.x + threadIdx.x;
    if (i < n) g_cnt[i] = 0;
}

__global__ void count_kernel(const void* __restrict__ ei, int E, int N) {
    int e = blockIdx.x * blockDim.x + threadIdx.x;
    if (e < E) {
        int s, d;
        load_edge(ei, E, e, g_is64, N, s, d);
        atomicAdd(&g_cnt[d], 1);
    }
}

// phase 1: per-block (1024 elems, 256 threads x 4) local exclusive scan + block sum
__global__ void scan1_kernel(int n) {
    __shared__ int wsum[8];
    int t = threadIdx.x;
    int lane = t & 31, wid = t >> 5;
    int i0 = blockIdx.x * SCAN_TILE + t * 4;

    int a0 = 0, a1 = 0, a2 = 0, a3 = 0;
    if (i0 + 3 < n) {
        int4 v = *(const int4*)&g_cnt[i0];
        a0 = v.x; a1 = v.y; a2 = v.z; a3 = v.w;
    } else {
        if (i0     < n) a0 = g_cnt[i0];
        if (i0 + 1 < n) a1 = g_cnt[i0 + 1];
        if (i0 + 2 < n) a2 = g_cnt[i0 + 2];
        if (i0 + 3 < n) a3 = g_cnt[i0 + 3];
    }
    int s = a0 + a1 + a2 + a3;

    int x = s;
    #pragma unroll
    for (int o = 1; o < 32; o <<= 1) {
        int y = __shfl_up_sync(0xFFFFFFFFu, x, o);
        if (lane >= o) x += y;
    }
    if (lane == 31) wsum[wid] = x;
    __syncthreads();
    if (t < 8) {
        int w = wsum[t];
        #pragma unroll
        for (int o = 1; o < 8; o <<= 1) {
            int y = __shfl_up_sync(0xFFu, w, o);
            if (t >= o) w += y;
        }
        wsum[t] = w;
    }
    __syncthreads();
    int excl = x - s + (wid > 0 ? wsum[wid - 1] : 0);

    if (i0     < n) g_off[i0]     = excl;
    if (i0 + 1 < n) g_off[i0 + 1] = excl + a0;
    if (i0 + 2 < n) g_off[i0 + 2] = excl + a0 + a1;
    if (i0 + 3 < n) g_off[i0 + 3] = excl + a0 + a1 + a2;
    if (t == 0) g_bsum[blockIdx.x] = wsum[7];
}

__global__ void scan2_kernel(int B, int n) {
    __shared__ int sh[128];
    int t = threadIdx.x;
    int v = (t < B) ? g_bsum[t] : 0;
    sh[t] = v;
    __syncthreads();
    for (int o = 1; o < 128; o <<= 1) {
        int y = (t >= o) ? sh[t - o] : 0;
        __syncthreads();
        sh[t] += y;
        __syncthreads();
    }
    if (t < B) g_bsum[t] = sh[t] - v;
    if (t == 127) g_off[n] = sh[127];
}

__global__ void scan3_kernel(int n) {
    int i0 = blockIdx.x * SCAN_TILE + threadIdx.x * 4;
    int bp = g_bsum[blockIdx.x];
    #pragma unroll
    for (int j = 0; j < 4; j++) {
        int i = i0 + j;
        if (i < n) {
            int v = g_off[i] + bp;
            g_off[i] = v;
            g_cur[i] = v;
        }
    }
}

__global__ void fill_kernel(const void* __restrict__ ei, int E, int N) {
    int e = blockIdx.x * blockDim.x + threadIdx.x;
    if (e < E) {
        int s, d;
        load_edge(ei, E, e, g_is64, N, s, d);
        int p = atomicAdd(&g_cur[d], 1);
        if (p >= 0 && p < MAXE) g_eidx[p] = s;
    }
}

// ---------------- aggregation: warp per node ----------------
__global__ void aggregate_kernel(const float* __restrict__ xext, int use_gh, int N) {
    int warp = (blockIdx.x * blockDim.x + threadIdx.x) >> 5;
    int lane = threadIdx.x & 31;
    if (warp >= N) return;
    const float4* feat = use_gh ? g_h : (const float4*)xext;

    int beg = g_off[warp];
    int end = g_off[warp + 1];
    int cnt = end - beg;

    float4 acc = make_float4(0.f, 0.f, 0.f, 0.f);
    int e = beg;
    for (; e + 4 <= end; e += 4) {
        int s0 = g_eidx[e + 0];
        int s1 = g_eidx[e + 1];
        int s2 = g_eidx[e + 2];
        int s3 = g_eidx[e + 3];
        float4 v0 = feat[(size_t)s0 * D4 + lane];
        float4 v1 = feat[(size_t)s1 * D4 + lane];
        float4 v2 = feat[(size_t)s2 * D4 + lane];
        float4 v3 = feat[(size_t)s3 * D4 + lane];
        acc.x += (v0.x + v1.x) + (v2.x + v3.x);
        acc.y += (v0.y + v1.y) + (v2.y + v3.y);
        acc.z += (v0.z + v1.z) + (v2.z + v3.z);
        acc.w += (v0.w + v1.w) + (v2.w + v3.w);
    }
    for (; e < end; e++) {
        int s = g_eidx[e];
        float4 v = feat[(size_t)s * D4 + lane];
        acc.x += v.x; acc.y += v.y; acc.z += v.z; acc.w += v.w;
    }
    float inv = 1.0f / fmaxf((float)cnt, 1.0f);
    acc.x *= inv; acc.y *= inv; acc.z *= inv; acc.w *= inv;
    g_mean[(size_t)warp * D4 + lane] = acc;
}

// ---------------- split-bf16 helpers ----------------
__device__ __forceinline__ void split_pack(float v0, float v1,
                                           uint32_t& hi, uint32_t& lo) {
    __nv_bfloat162 h = __floats2bfloat162_rn(v0, v1);   // .x = v0 (low 16b)
    float r0 = v0 - __bfloat162float(h.x);
    float r1 = v1 - __bfloat162float(h.y);
    __nv_bfloat162 l = __floats2bfloat162_rn(r0, r1);
    hi = *(uint32_t*)&h;
    lo = *(uint32_t*)&l;
}

__device__ __forceinline__ void mma_bf16(float* c, const uint32_t* a, const uint32_t* b) {
    asm volatile(
        "mma.sync.aligned.m16n8k16.row.col.f32.bf16.bf16.f32 "
        "{%0,%1,%2,%3}, {%4,%5,%6,%7}, {%8,%9}, {%0,%1,%2,%3};"
        : "+f"(c[0]), "+f"(c[1]), "+f"(c[2]), "+f"(c[3])
        : "r"(a[0]), "r"(a[1]), "r"(a[2]), "r"(a[3]), "r"(b[0]), "r"(b[1]));
}

// ---------------- split-bf16 tensor-core fused SAGE GEMM ----------------
// out[i][:] = g_mean[i] @ Wl + in[i] @ Wr + b     (K = 256 concat)
// block: 64 rows x 128 cols, 256 threads (8 warps, 2x4 warp grid)
__global__ void gemm_mma_kernel(const float* __restrict__ xext, int use_gh_in,
                                const float* __restrict__ Wl,
                                const float* __restrict__ Wr,
                                const float* __restrict__ bias,
                                float* __restrict__ oext, int use_gh_out,
                                int nrows) {
    extern __shared__ uint32_t sm[];
    uint32_t* sWh  = sm;                       // [K2][SW_STRIDE]
    uint32_t* sWlo = sm + SW_WORDS;
    uint32_t* sAh  = sm + 2 * SW_WORDS;        // [K2][SA_STRIDE]
    uint32_t* sAlo = sm + 2 * SW_WORDS + SA_WORDS;

    const float* xin = use_gh_in ? (const float*)g_h : xext;
    const float* meanf = (const float*)g_mean;
    float* out = use_gh_out ? (float*)g_h : oext;

    int tid = threadIdx.x;
    int row0 = blockIdx.x * BLK_M;

    // --- weights: 128 kk-pairs x 128 n ---
    for (int i = tid; i < K2 * 128; i += 256) {
        int kk = i >> 7;
        int n = i & 127;
        const float* W = (kk < 64) ? Wl : Wr;
        int k0 = (kk & 63) * 2;
        float w0 = W[k0 * 128 + n];
        float w1 = W[(k0 + 1) * 128 + n];
        uint32_t hi, lo;
        split_pack(w0, w1, hi, lo);
        sWh[kk * SW_STRIDE + n] = hi;
        sWlo[kk * SW_STRIDE + n] = lo;
    }

    // --- A tile: 64 rows x 128 kk-pairs (kk<64: mean, else x) ---
    for (int i = tid; i < BLK_M * K2; i += 256) {
        int kk = i & 127;
        int row = i >> 7;
        int gr = row0 + row;
        if (gr >= nrows) gr = nrows - 1;
        float v0, v1;
        if (kk < 64) {
            v0 = meanf[(size_t)gr * D + 2 * kk];
            v1 = meanf[(size_t)gr * D + 2 * kk + 1];
        } else {
            v0 = xin[(size_t)gr * D + 2 * kk - 128];
            v1 = xin[(size_t)gr * D + 2 * kk - 127];
        }
        uint32_t hi, lo;
        split_pack(v0, v1, hi, lo);
        sAh[kk * SA_STRIDE + row] = hi;
        sAlo[kk * SA_STRIDE + row] = lo;
    }
    __syncthreads();

    int lane = tid & 31;
    int warp = tid >> 5;
    int g = lane >> 2;       // group (0..7)
    int tig = lane & 3;      // thread-in-group
    int wm = warp & 1;
    int wn = warp >> 1;
    int m0 = wm * 32;
    int n0 = wn * 32;

    float acc[2][4][4];
    #pragma unroll
    for (int mf = 0; mf < 2; mf++)
        #pragma unroll
        for (int nf = 0; nf < 4; nf++)
            #pragma unroll
            for (int q = 0; q < 4; q++) acc[mf][nf][q] = 0.f;

    for (int s = 0; s < 16; s++) {
        int kb = s * 8;
        uint32_t ah[2][4], al[2][4];
        #pragma unroll
        for (int mf = 0; mf < 2; mf++) {
            int rb = m0 + mf * 16 + g;
            int i0 = (kb + tig) * SA_STRIDE + rb;
            int i1 = (kb + 4 + tig) * SA_STRIDE + rb;
            ah[mf][0] = sAh[i0];  ah[mf][1] = sAh[i0 + 8];
            ah[mf][2] = sAh[i1];  ah[mf][3] = sAh[i1 + 8];
            al[mf][0] = sAlo[i0]; al[mf][1] = sAlo[i0 + 8];
            al[mf][2] = sAlo[i1]; al[mf][3] = sAlo[i1 + 8];
        }
        uint32_t bh[4][2], bl[4][2];
        #pragma unroll
        for (int nf = 0; nf < 4; nf++) {
            int n = n0 + nf * 8 + g;
            bh[nf][0] = sWh[(kb + tig) * SW_STRIDE + n];
            bh[nf][1] = sWh[(kb + 4 + tig) * SW_STRIDE + n];
            bl[nf][0] = sWlo[(kb + tig) * SW_STRIDE + n];
            bl[nf][1] = sWlo[(kb + 4 + tig) * SW_STRIDE + n];
        }
        #pragma unroll
        for (int mf = 0; mf < 2; mf++)
            #pragma unroll
            for (int nf = 0; nf < 4; nf++) {
                mma_bf16(acc[mf][nf], ah[mf], bh[nf]);   // Ah*Bh
                mma_bf16(acc[mf][nf], ah[mf], bl[nf]);   // Ah*Bl
                mma_bf16(acc[mf][nf], al[mf], bh[nf]);   // Al*Bh
            }
    }

    // --- epilogue ---
    #pragma unroll
    for (int nf = 0; nf < 4; nf++) {
        int col = n0 + nf * 8 + 2 * tig;
        float2 bv = *(const float2*)&bias[col];
        #pragma unroll
        for (int mf = 0; mf < 2; mf++) {
            int r0 = row0 + m0 + mf * 16 + g;
            int r1 = r0 + 8;
            if (r0 < nrows) {
                float2 o = make_float2(acc[mf][nf][0] + bv.x, acc[mf][nf][1] + bv.y);
                *(float2*)&out[(size_t)r0 * D + col] = o;
            }
            if (r1 < nrows) {
                float2 o = make_float2(acc[mf][nf][2] + bv.x, acc[mf][nf][3] + bv.y);
                *(float2*)&out[(size_t)r1 * D + col] = o;
            }
        }
    }
}

// ---------------- launch ----------------
extern "C" void kernel_launch(void* const* d_in, const int* in_sizes, int n_in,
                              void* d_out, int out_size) {
    const float* x  = (const float*)d_in[0];
    const void*  ei = d_in[1];
    int off = n_in - 6;
    const float* Wl1 = (const float*)d_in[off + 0];
    const float* bl1 = (const float*)d_in[off + 1];
    const float* Wr1 = (const float*)d_in[off + 2];
    const float* Wl2 = (const float*)d_in[off + 3];
    const float* bl2 = (const float*)d_in[off + 4];
    const float* Wr2 = (const float*)d_in[off + 5];

    int N = in_sizes[0] / D;
    int E = in_sizes[1] / 2;
    int ORIGN = out_size / D;
    float* out = (float*)d_out;

    cudaFuncSetAttribute(gemm_mma_kernel,
                         cudaFuncAttributeMaxDynamicSharedMemorySize, GEMM_SMEM_BYTES);

    // ---- dtype detect + CSR build (dst-grouped) ----
    detect_kernel<<<1, 1024>>>((const unsigned long long*)ei, E);
    zero_cnt_kernel<<<(N + 255) / 256, 256>>>(N);
    count_kernel<<<(E + 255) / 256, 256>>>(ei, E, N);
    int B = (N + SCAN_TILE - 1) / SCAN_TILE;           // 98
    scan1_kernel<<<B, 256>>>(N);
    scan2_kernel<<<1, 128>>>(B, N);
    scan3_kernel<<<B, 256>>>(N);
    fill_kernel<<<(E + 255) / 256, 256>>>(ei, E, N);

    int aggGrid = (N * 32 + 255) / 256;
    int gemmGrid1 = (N + BLK_M - 1) / BLK_M;
    int gemmGrid2 = (ORIGN + BLK_M - 1) / BLK_M;

    // ---- layer 1: mean(x) -> g_mean ; g_h = mean@Wl1 + x@Wr1 + b1 ----
    aggregate_kernel<<<aggGrid, 256>>>(x, 0, N);
    gemm_mma_kernel<<<gemmGrid1, 256, GEMM_SMEM_BYTES>>>(
        x, 0, Wl1, Wr1, bl1, nullptr, 1, N);

    // ---- layer 2: mean(g_h) -> g_mean ; out = mean@Wl2 + g_h@Wr2 + b2 ----
    aggregate_kernel<<<aggGrid, 256>>>(nullptr, 1, N);
    gemm_mma_kernel<<<gemmGrid2, 256, GEMM_SMEM_BYTES>>>(
        nullptr, 1, Wl2, Wr2, bl2, out, 0, ORIGN);
}